// round 15
// baseline (speedup 1.0000x reference)
#include <cuda_runtime.h>

// IWT (inverse Haar) — fixed shapes from setup_inputs():
//   x:   [B=8, 4*C=256, H=256, W=256] float32
//   out: [B=8, C=64, 2H=512, 2W=512] float32
//
// out[b,c,2h+p,2w+q] = 0.25 * ( LL +/- LH +/- HL +/- HH ) butterfly.
//
// R12 dense-store mapping (best: 156.2us, DRAM 86.1%, 18 regs) + 2 independent
// items per thread (item1 = tid + TOTAL/2, i.e. batches 0-3 vs 4-7):
// 8 front-batched LDG.64 -> 2x per-warp MLP. launch_bounds(128,16) caps regs
// at 32 so occupancy stays at the full 2048 threads/SM (fixes R7's failure).

#define IWT_B  8
#define IWT_C  64
#define IWT_H  256
#define IWT_W  256
#define IWT_W2 (IWT_W / 2)           // 128 float2 per input row
#define IWT_HW2 (IWT_H * IWT_W2)     // float2 per (subband,channel) plane = 32768
#define IWT_OROW4 (2 * IWT_W / 4)    // 128 float4 per output row
#define IWT_TOTAL2 (IWT_B * IWT_C * IWT_H * IWT_W2)  // 16,777,216 items
#define IWT_HALF2 (IWT_TOTAL2 / 2)
#define IWT_TPB 128

__device__ __forceinline__ void iwt_decode(unsigned tid, unsigned& in_base,
                                           unsigned& out_base) {
    unsigned w2 = tid & (IWT_W2 - 1);
    unsigned t1 = tid >> 7;
    unsigned h  = t1 & (IWT_H - 1);
    unsigned t2 = t1 >> 8;
    unsigned c  = t2 & (IWT_C - 1);
    unsigned b  = t2 >> 6;
    in_base  = (b * 4u * IWT_C + c) * IWT_HW2 + h * IWT_W2 + w2;
    out_base = ((b * IWT_C + c) * (2 * IWT_H) + 2 * h) * IWT_OROW4 + w2;
}

__device__ __forceinline__ void iwt_compute(const float2& ll, const float2& lh,
                                            const float2& hl, const float2& hh,
                                            float4& row0, float4& row1) {
    float s_pp0 = (ll.x + lh.x) * 0.25f;
    float s_pm0 = (ll.x - lh.x) * 0.25f;
    float t_pp0 = (hl.x + hh.x) * 0.25f;
    float t_pm0 = (hl.x - hh.x) * 0.25f;
    float s_pp1 = (ll.y + lh.y) * 0.25f;
    float s_pm1 = (ll.y - lh.y) * 0.25f;
    float t_pp1 = (hl.y + hh.y) * 0.25f;
    float t_pm1 = (hl.y - hh.y) * 0.25f;
    row0 = make_float4(s_pp0 + t_pp0, s_pp0 - t_pp0,
                       s_pp1 + t_pp1, s_pp1 - t_pp1);
    row1 = make_float4(s_pm0 + t_pm0, s_pm0 - t_pm0,
                       s_pm1 + t_pm1, s_pm1 - t_pm1);
}

__global__ void __launch_bounds__(IWT_TPB, 16) iwt_kernel(const float2* __restrict__ x,
                                                          float4* __restrict__ y) {
    unsigned tid = blockIdx.x * (unsigned)IWT_TPB + threadIdx.x;

    unsigned ib0, ob0, ib1, ob1;
    iwt_decode(tid, ib0, ob0);
    iwt_decode(tid + IWT_HALF2, ib1, ob1);

    const unsigned P = IWT_C * IWT_HW2;  // subband plane stride (float2)

    // 8 independent front-batched loads
    float2 ll0 = __ldcs(&x[ib0]);
    float2 lh0 = __ldcs(&x[ib0 + 1u * P]);
    float2 hl0 = __ldcs(&x[ib0 + 2u * P]);
    float2 hh0 = __ldcs(&x[ib0 + 3u * P]);
    float2 ll1 = __ldcs(&x[ib1]);
    float2 lh1 = __ldcs(&x[ib1 + 1u * P]);
    float2 hl1 = __ldcs(&x[ib1 + 2u * P]);
    float2 hh1 = __ldcs(&x[ib1 + 3u * P]);

    float4 a0, a1, b0, b1;
    iwt_compute(ll0, lh0, hl0, hh0, a0, a1);
    iwt_compute(ll1, lh1, hl1, hh1, b0, b1);

    __stcs(&y[ob0],             a0);
    __stcs(&y[ob0 + IWT_OROW4], a1);
    __stcs(&y[ob1],             b0);
    __stcs(&y[ob1 + IWT_OROW4], b1);
}

extern "C" void kernel_launch(void* const* d_in, const int* in_sizes, int n_in,
                              void* d_out, int out_size) {
    const float2* x = (const float2*)d_in[0];
    float4* y = (float4*)d_out;
    // 8,388,608 threads (2 items each) -> 65536 blocks of 128
    iwt_kernel<<<IWT_HALF2 / IWT_TPB, IWT_TPB>>>(x, y);
}